// round 3
// baseline (speedup 1.0000x reference)
#include <cuda_runtime.h>
#include <cuda_fp16.h>

typedef unsigned long long u64;

#define N_NODES 50000
#define N_EDGES 800000
#define N_GRAPHS 64
#define EMB_DIM 128
#define IMG_DIM 4096
#define N_TYPES 30
#define CAT_DIM (IMG_DIM + EMB_DIM)   // 4224

#define IMG_SPLITS 8
#define IMG_KC 512
#define HEAD_KC 128
#define HI_SPLITS 32                  // 4096/128
#define HC_SPLITS 33                  // 4224/128
#define IMG_BLOCKS (64 * IMG_SPLITS)  // 512
#define AGG_BLOCKS ((N_NODES + 7) / 8)

// ---------------- device scratch ------------------------------------------------
__device__ float g_dis[N_NODES];
__device__ int   g_cnt_e[N_NODES];
__device__ int   g_offs[N_NODES + 1];
__device__ int   g_cursor[N_NODES];
__device__ int2  g_epack[N_EDGES];
__device__ int   g_goff[N_GRAPHS + 1];

__device__ __half g_XWh[N_NODES * EMB_DIM];   // half hand-off buffer (all 3 layers)
__device__ __half g_TXWh[N_TYPES * EMB_DIM];
__device__ float g_bufA[N_NODES * EMB_DIM];
__device__ float g_bufB[N_NODES * EMB_DIM];
__device__ float g_xc[N_GRAPHS * CAT_DIM];    // [xi | pooled]
__device__ float g_ipart[IMG_SPLITS * 64 * IMG_DIM];
__device__ float g_hpi[HI_SPLITS * 64 * EMB_DIM];
__device__ float g_hpc[HC_SPLITS * 64 * EMB_DIM];

// ---------------- f32x2 helpers -------------------------------------------------
__device__ __forceinline__ void ffma2(u64& d, u64 a, u64 b) {
    asm("fma.rn.f32x2 %0, %1, %2, %0;" : "+l"(d) : "l"(a), "l"(b));
}
__device__ __forceinline__ float2 upk(u64 v) {
    float2 r; asm("mov.b64 {%0,%1}, %2;" : "=f"(r.x), "=f"(r.y) : "l"(v)); return r;
}

// ---------------- preprocessing -------------------------------------------------
__global__ void k_init() {
    int i = blockIdx.x * blockDim.x + threadIdx.x;
    if (i < N_NODES) { g_dis[i] = 1.0f; g_cnt_e[i] = 0; g_cursor[i] = 0; }
}

__global__ void k_deg(const int* __restrict__ ei, const float* __restrict__ ea,
                      const int* __restrict__ batch) {
    int i = blockIdx.x * blockDim.x + threadIdx.x;
    if (i < N_EDGES) {
        int c = ei[N_EDGES + i];
        atomicAdd(&g_dis[c], ea[i]);
        atomicAdd(&g_cnt_e[c], 1);
    }
    if (i < N_NODES) {
        int b = batch[i];
        if (i == 0) {
            for (int g = 0; g <= b; g++) g_goff[g] = 0;
        } else {
            int pb = batch[i - 1];
            for (int g = pb + 1; g <= b; g++) g_goff[g] = i;
        }
        if (i == N_NODES - 1)
            for (int g = b + 1; g <= N_GRAPHS; g++) g_goff[g] = N_NODES;
    }
}

__global__ void k_scan() {
    __shared__ int sh[1024];
    const int C = (N_NODES + 1023) / 1024;
    int t = threadIdx.x;
    int base = t * C;
    int sum = 0;
    for (int j = 0; j < C; j++) { int i = base + j; if (i < N_NODES) sum += g_cnt_e[i]; }
    sh[t] = sum;
    __syncthreads();
    for (int off = 1; off < 1024; off <<= 1) {
        int v = (t >= off) ? sh[t - off] : 0;
        __syncthreads();
        sh[t] += v;
        __syncthreads();
    }
    int prefix = t ? sh[t - 1] : 0;
    for (int j = 0; j < C; j++) {
        int i = base + j;
        if (i < N_NODES) { int c = g_cnt_e[i]; g_offs[i] = prefix; prefix += c; }
    }
    if (t == 1023) g_offs[N_NODES] = sh[1023];
    for (int i = t; i < N_NODES; i += 1024) g_dis[i] = rsqrtf(g_dis[i]);
}

// 4 grid-strided edges per thread for atomic MLP
__global__ void k_scatter(const int* __restrict__ ei, const float* __restrict__ ea) {
    int stride = gridDim.x * blockDim.x;
    int e = blockIdx.x * blockDim.x + threadIdx.x;
    #pragma unroll
    for (int j = 0; j < 4; j++, e += stride) {
        if (e >= N_EDGES) break;
        int r = ei[e], c = ei[N_EDGES + e];
        float coef = g_dis[r] * ea[e] * g_dis[c];
        int pos = g_offs[c] + atomicAdd(&g_cursor[c], 1);
        g_epack[pos] = make_int2(r, __float_as_int(coef));
    }
}

// ---------------- layer-1 table trick -------------------------------------------
__global__ void k_table_gemm(const float* __restrict__ emb, const float* __restrict__ W1) {
    __shared__ float xr[EMB_DIM];
    int t = blockIdx.x, d = threadIdx.x;
    xr[d] = emb[t * EMB_DIM + d];
    __syncthreads();
    const float* w = &W1[d * EMB_DIM];
    float s = 0.f;
    #pragma unroll 8
    for (int k = 0; k < EMB_DIM; k++) s += xr[k] * w[k];
    g_TXWh[t * EMB_DIM + d] = __float2half(s);
}

// gather half rows: 16 threads/node, 16B each
__global__ void k_gather(const int* __restrict__ types) {
    int t = blockIdx.x * blockDim.x + threadIdx.x;
    if (t >= N_NODES * 16) return;
    int i = t >> 4, j = (t & 15) << 3;
    *(uint4*)&g_XWh[i * EMB_DIM + j] = *(const uint4*)&g_TXWh[types[i] * EMB_DIM + j];
}

// ---------------- CSR aggregation (warp per node, half gather) ------------------
template <bool RELU>
__device__ __forceinline__ void agg_body(const float* __restrict__ bias,
                                         float* __restrict__ out, int bid) {
    int node = bid * 8 + ((int)threadIdx.x >> 5);
    if (node >= N_NODES) return;
    int lane = threadIdx.x & 31;
    const __half2* xh = (const __half2*)g_XWh;     // 64 half2 per row
    int s = g_offs[node], e = g_offs[node + 1];
    float4 a0 = make_float4(0.f, 0.f, 0.f, 0.f);
    float4 a1 = make_float4(0.f, 0.f, 0.f, 0.f);
    int p = s;
    for (; p + 1 < e; p += 2) {
        int2 e0 = g_epack[p], e1 = g_epack[p + 1];
        uint2 r0 = *(const uint2*)(xh + (size_t)e0.x * 64 + lane * 2);
        uint2 r1 = *(const uint2*)(xh + (size_t)e1.x * 64 + lane * 2);
        float c0 = __int_as_float(e0.y), c1 = __int_as_float(e1.y);
        float2 f00 = __half22float2(*(__half2*)&r0.x), f01 = __half22float2(*(__half2*)&r0.y);
        float2 f10 = __half22float2(*(__half2*)&r1.x), f11 = __half22float2(*(__half2*)&r1.y);
        a0.x += c0 * f00.x; a0.y += c0 * f00.y; a0.z += c0 * f01.x; a0.w += c0 * f01.y;
        a1.x += c1 * f10.x; a1.y += c1 * f10.y; a1.z += c1 * f11.x; a1.w += c1 * f11.y;
    }
    if (p < e) {
        int2 e0 = g_epack[p];
        uint2 r0 = *(const uint2*)(xh + (size_t)e0.x * 64 + lane * 2);
        float c0 = __int_as_float(e0.y);
        float2 f00 = __half22float2(*(__half2*)&r0.x), f01 = __half22float2(*(__half2*)&r0.y);
        a0.x += c0 * f00.x; a0.y += c0 * f00.y; a0.z += c0 * f01.x; a0.w += c0 * f01.y;
    }
    a0.x += a1.x; a0.y += a1.y; a0.z += a1.z; a0.w += a1.w;
    float d2 = g_dis[node]; d2 *= d2;
    uint2 rv = *(const uint2*)(xh + (size_t)node * 64 + lane * 2);
    float2 v0 = __half22float2(*(__half2*)&rv.x), v1 = __half22float2(*(__half2*)&rv.y);
    float4 b = *(const float4*)&bias[lane * 4];
    a0.x += d2 * v0.x + b.x; a0.y += d2 * v0.y + b.y;
    a0.z += d2 * v1.x + b.z; a0.w += d2 * v1.y + b.w;
    if (RELU) {
        a0.x = fmaxf(a0.x, 0.f); a0.y = fmaxf(a0.y, 0.f);
        a0.z = fmaxf(a0.z, 0.f); a0.w = fmaxf(a0.w, 0.f);
    }
    *(float4*)&out[(size_t)node * EMB_DIM + lane * 4] = a0;
}

template <bool RELU>
__global__ void __launch_bounds__(256) k_agg(const float* __restrict__ bias,
                                             float* __restrict__ out) {
    agg_body<RELU>(bias, out, blockIdx.x);
}

// ---------------- 64x64 SGEMM tile with FFMA2 -----------------------------------
// C = A(MxK) * B(NxK)^T ; OUT_HALF: write half rows (ld 128) else fp32 (ldc)
template <bool OUT_HALF>
__device__ __forceinline__ void sgemm64(const float* __restrict__ A, int lda,
                                        const float* __restrict__ B, int ldb,
                                        float* __restrict__ C, int ldc,
                                        __half* __restrict__ Ch,
                                        int m0, int n0, int k0, int klen,
                                        int M, int N) {
    __shared__ float Asd[16][136];    // duplicated (a,a) pairs, 64 m -> 128 floats
    __shared__ float Bs[16][68];
    int t = threadIdx.x;
    int tn = t & 15, tm = t >> 4;
    int lrow = t >> 2, lkq = (t & 3) << 2;

    u64 cc[4][2];
    #pragma unroll
    for (int i = 0; i < 4; i++) { cc[i][0] = 0ull; cc[i][1] = 0ull; }

    for (int kk = k0; kk < k0 + klen; kk += 16) {
        float4 a;
        int am = m0 + lrow;
        if (am < M) a = *(const float4*)&A[(size_t)am * lda + kk + lkq];
        else        a = make_float4(0.f, 0.f, 0.f, 0.f);
        *(float2*)&Asd[lkq + 0][2 * lrow] = make_float2(a.x, a.x);
        *(float2*)&Asd[lkq + 1][2 * lrow] = make_float2(a.y, a.y);
        *(float2*)&Asd[lkq + 2][2 * lrow] = make_float2(a.z, a.z);
        *(float2*)&Asd[lkq + 3][2 * lrow] = make_float2(a.w, a.w);
        int bn = n0 + lrow;
        float4 b;
        if (bn < N) b = *(const float4*)&B[(size_t)bn * ldb + kk + lkq];
        else        b = make_float4(0.f, 0.f, 0.f, 0.f);
        Bs[lkq + 0][lrow] = b.x; Bs[lkq + 1][lrow] = b.y;
        Bs[lkq + 2][lrow] = b.z; Bs[lkq + 3][lrow] = b.w;
        __syncthreads();
        #pragma unroll
        for (int k = 0; k < 16; k++) {
            u64 b01 = *(const u64*)&Bs[k][tn * 4];
            u64 b23 = *(const u64*)&Bs[k][tn * 4 + 2];
            u64 a0 = *(const u64*)&Asd[k][2 * (tm * 4 + 0)];
            u64 a1 = *(const u64*)&Asd[k][2 * (tm * 4 + 1)];
            u64 a2 = *(const u64*)&Asd[k][2 * (tm * 4 + 2)];
            u64 a3 = *(const u64*)&Asd[k][2 * (tm * 4 + 3)];
            ffma2(cc[0][0], a0, b01); ffma2(cc[0][1], a0, b23);
            ffma2(cc[1][0], a1, b01); ffma2(cc[1][1], a1, b23);
            ffma2(cc[2][0], a2, b01); ffma2(cc[2][1], a2, b23);
            ffma2(cc[3][0], a3, b01); ffma2(cc[3][1], a3, b23);
        }
        __syncthreads();
    }
    #pragma unroll
    for (int i = 0; i < 4; i++) {
        int m = m0 + tm * 4 + i;
        if (m >= M) continue;
        float2 lo = upk(cc[i][0]), hi = upk(cc[i][1]);
        if (OUT_HALF) {
            __half2* dst = (__half2*)&Ch[(size_t)m * EMB_DIM + n0 + tn * 4];
            dst[0] = __floats2half2_rn(lo.x, lo.y);
            dst[1] = __floats2half2_rn(hi.x, hi.y);
        } else {
            float* dst = &C[(size_t)m * ldc + n0 + tn * 4];
            dst[0] = lo.x; dst[1] = lo.y; dst[2] = hi.x; dst[3] = hi.y;
        }
    }
}

// node GEMM: [N_NODES,128] x [128,128]^T -> half g_XWh
__global__ void __launch_bounds__(256) k_gemm128(const float* __restrict__ A,
                                                 const float* __restrict__ B) {
    sgemm64<true>(A, EMB_DIM, B, EMB_DIM, nullptr, 0, g_XWh,
                  blockIdx.y * 64, blockIdx.x * 64, 0, EMB_DIM, N_NODES, EMB_DIM);
}

// split-K partials, M=64
__global__ void __launch_bounds__(256) k_splitk(const float* __restrict__ A, int lda,
                                                const float* __restrict__ B, int ldb,
                                                float* __restrict__ part, int N, int KC) {
    int z = blockIdx.z;
    sgemm64<false>(A, lda, B, ldb, part + (size_t)z * 64 * N, N, nullptr,
                   0, blockIdx.x * 64, z * KC, KC, 64, N);
}

// fused: image split-K GEMM + layer-1 aggregation
__global__ void __launch_bounds__(256) k_fused(const float* __restrict__ images,
                                               const float* __restrict__ W_img,
                                               const float* __restrict__ b1) {
    if (blockIdx.x < IMG_BLOCKS) {
        int ntile = blockIdx.x & 63, z = blockIdx.x >> 6;
        sgemm64<false>(images, IMG_DIM, W_img, IMG_DIM,
                       g_ipart + (size_t)z * 64 * IMG_DIM, IMG_DIM, nullptr,
                       0, ntile * 64, z * IMG_KC, IMG_KC, 64, IMG_DIM);
    } else {
        agg_body<true>(b1, g_bufA, blockIdx.x - IMG_BLOCKS);
    }
}

__global__ void k_img_reduce(const float* __restrict__ b_img) {
    int i = blockIdx.x * blockDim.x + threadIdx.x;
    if (i >= 64 * IMG_DIM) return;
    int m = i >> 12, n = i & (IMG_DIM - 1);
    float v = b_img[n];
    #pragma unroll
    for (int z = 0; z < IMG_SPLITS; z++)
        v += g_ipart[((size_t)z * 64 + m) * IMG_DIM + n];
    g_xc[m * CAT_DIM + n] = v;
}

__global__ void __launch_bounds__(512) k_pool_seg(const float* __restrict__ xg) {
    __shared__ float sh[512];
    int g = blockIdx.x;
    int d = threadIdx.x & 127, l4 = threadIdx.x >> 7;
    int s = g_goff[g], e = g_goff[g + 1];
    float acc = 0.f;
    for (int i = s + l4; i < e; i += 4) acc += xg[(size_t)i * EMB_DIM + d];
    sh[threadIdx.x] = acc;
    __syncthreads();
    if (threadIdx.x < 128) {
        float v = sh[d] + sh[128 + d] + sh[256 + d] + sh[384 + d];
        float c = fmaxf((float)(e - s), 1.f);
        g_xc[g * CAT_DIM + IMG_DIM + d] = v / c;
    }
}

__global__ void k_headnorm(const float* __restrict__ bi, const float* __restrict__ bc,
                           float* __restrict__ out) {
    __shared__ float sh[4];
    int which = blockIdx.x >> 6, m = blockIdx.x & 63, n = threadIdx.x;
    float v;
    if (which == 0) {
        v = bi[n];
        #pragma unroll
        for (int z = 0; z < HI_SPLITS; z++) v += g_hpi[(z * 64 + m) * EMB_DIM + n];
    } else {
        v = bc[n];
        #pragma unroll
        for (int z = 0; z < HC_SPLITS; z++) v += g_hpc[(z * 64 + m) * EMB_DIM + n];
    }
    float s = v * v;
    #pragma unroll
    for (int o = 16; o; o >>= 1) s += __shfl_xor_sync(0xffffffffu, s, o);
    if ((n & 31) == 0) sh[n >> 5] = s;
    __syncthreads();
    float tot = sh[0] + sh[1] + sh[2] + sh[3];
    out[blockIdx.x * EMB_DIM + n] = v * rsqrtf(tot);
}

// ---------------- host ----------------------------------------------------------
extern "C" void kernel_launch(void* const* d_in, const int* in_sizes, int n_in,
                              void* d_out, int out_size) {
    const float* images = (const float*)d_in[0];
    const int*   ntypes = (const int*)  d_in[1];
    const int*   eidx   = (const int*)  d_in[2];
    const float* eattr  = (const float*)d_in[3];
    const int*   batch  = (const int*)  d_in[4];
    const float* emb    = (const float*)d_in[5];
    const float* W_img  = (const float*)d_in[6];
    const float* b_img  = (const float*)d_in[7];
    const float* W1     = (const float*)d_in[8];
    const float* b1     = (const float*)d_in[9];
    const float* W2     = (const float*)d_in[10];
    const float* b2     = (const float*)d_in[11];
    const float* W3     = (const float*)d_in[12];
    const float* b3     = (const float*)d_in[13];
    const float* Wi     = (const float*)d_in[14];
    const float* bi     = (const float*)d_in[15];
    const float* Wc     = (const float*)d_in[16];
    const float* bc     = (const float*)d_in[17];
    float* out = (float*)d_out;

    float *p_bufA, *p_bufB, *p_xc, *p_hpi, *p_hpc;
    cudaGetSymbolAddress((void**)&p_bufA, g_bufA);
    cudaGetSymbolAddress((void**)&p_bufB, g_bufB);
    cudaGetSymbolAddress((void**)&p_xc,   g_xc);
    cudaGetSymbolAddress((void**)&p_hpi,  g_hpi);
    cudaGetSymbolAddress((void**)&p_hpc,  g_hpc);

    const int T = 256;
    int nb_nodes = (N_NODES + T - 1) / T;
    int nb_edges = (N_EDGES + T - 1) / T;
    int nb_scat  = (N_EDGES / 4 + T - 1) / T;

    // graph preprocessing
    k_init<<<nb_nodes, T>>>();
    k_deg<<<nb_edges, T>>>(eidx, eattr, batch);
    k_scan<<<1, 1024>>>();
    k_scatter<<<nb_scat, T>>>(eidx, eattr);

    // layer-1 inputs
    k_table_gemm<<<N_TYPES, EMB_DIM>>>(emb, W1);
    k_gather<<<(N_NODES * 16 + T - 1) / T, T>>>(ntypes);

    // fused image GEMM + layer-1 agg
    k_fused<<<IMG_BLOCKS + AGG_BLOCKS, T>>>(images, W_img, b1);
    k_img_reduce<<<(64 * IMG_DIM + T - 1) / T, T>>>(b_img);

    // oi head early (depends only on xi) — overlaps graph chain
    k_splitk<<<dim3(2, 1, HI_SPLITS), T>>>(p_xc, CAT_DIM, Wi, IMG_DIM, p_hpi, EMB_DIM, HEAD_KC);

    // layer 2
    k_gemm128<<<dim3(2, (N_NODES + 63) / 64), T>>>(p_bufA, W2);
    k_agg<true><<<AGG_BLOCKS, T>>>(b2, p_bufB);

    // layer 3
    k_gemm128<<<dim3(2, (N_NODES + 63) / 64), T>>>(p_bufB, W3);
    k_agg<false><<<AGG_BLOCKS, T>>>(b3, p_bufA);

    // pooling -> g_xc[:, 4096:]
    k_pool_seg<<<N_GRAPHS, 512>>>(p_bufA);

    // oc head + fused reduce/normalize
    k_splitk<<<dim3(2, 1, HC_SPLITS), T>>>(p_xc, CAT_DIM, Wc, CAT_DIM, p_hpc, EMB_DIM, HEAD_KC);
    k_headnorm<<<2 * 64, EMB_DIM>>>(bi, bc, out);

    (void)in_sizes; (void)n_in; (void)out_size;
}